// round 16
// baseline (speedup 1.0000x reference)
#include <cuda_runtime.h>
#include <cuda_fp16.h>
#include <math.h>
#include <stdint.h>

// ---------------------------------------------------------------------------
// Problem constants
// ---------------------------------------------------------------------------
#define BATCH 8
#define SEQ   2048
#define DIM   768
#define BS    (BATCH * SEQ)   // 16384

// ---------------------------------------------------------------------------
// Scratch (__device__ globals; no allocation allowed). All fp16 single-word.
// ---------------------------------------------------------------------------
__device__ __half g_xh [(size_t)BS * DIM];
__device__ __half g_wt [3ULL * DIM * DIM];            // W^T, [z][n][k]
__device__ __half g_qh [(size_t)BS * DIM];            // Q (pre-scaled by alpha)
__device__ __half g_kh [(size_t)BS * DIM];            // K
__device__ __half g_vth[(size_t)BATCH * DIM * SEQ];   // V^T: [b][d][s]
__device__ __half g_ph [(size_t)BATCH * SEQ * SEQ];   // un-normalized exp(S)
__device__ float  g_rsum[(size_t)BATCH * SEQ];        // per-row sum of exp

// ---------------------------------------------------------------------------
// Helpers
// ---------------------------------------------------------------------------
__device__ __forceinline__ uint32_t smem_u32(const void* p) {
    uint32_t a;
    asm("{ .reg .u64 t; cvta.to.shared.u64 t, %1; cvt.u32.u64 %0, t; }"
        : "=r"(a) : "l"(p));
    return a;
}

#define LDSM4(r, addr) \
    asm volatile("ldmatrix.sync.aligned.m8n8.x4.shared.b16 {%0,%1,%2,%3}, [%4];" \
        : "=r"((r)[0]), "=r"((r)[1]), "=r"((r)[2]), "=r"((r)[3]) : "r"(addr))

#define MMA_F16(d, a, b) \
    asm volatile("mma.sync.aligned.m16n8k16.row.col.f32.f16.f16.f32 " \
        "{%0,%1,%2,%3}, {%4,%5,%6,%7}, {%8,%9}, {%0,%1,%2,%3};" \
        : "+f"((d)[0]), "+f"((d)[1]), "+f"((d)[2]), "+f"((d)[3]) \
        : "r"((a)[0]), "r"((a)[1]), "r"((a)[2]), "r"((a)[3]), \
          "r"((b)[0]), "r"((b)[1]))

#define CP_ASYNC16(dst, src) \
    asm volatile("cp.async.cg.shared.global [%0], [%1], 16;" \
        :: "r"(dst), "l"(src))
#define CP_COMMIT()  asm volatile("cp.async.commit_group;")
#define CP_WAIT1()   asm volatile("cp.async.wait_group 1;")
#define CP_WAIT0()   asm volatile("cp.async.wait_group 0;")

// ---------------------------------------------------------------------------
// GEMM tiling: BM=128, BN=128, BK=64 fp16; 4 warps (2m x 2n), warp 64x64.
// Stage = A tile + B tile (16KB each) = 32KB, XOR-swizzled rows.
// 3-stage ring = 96KB/CTA; 128 threads, <=255 regs -> 2 CTAs/SM.
// ---------------------------------------------------------------------------
#define NTHREADS 128
#define TILE_B   16384
#define STAGE_B  (2 * TILE_B)              // 32768
#define NSTAGE   3
#define SMEM_TOTAL (NSTAGE * STAGE_B)      // 98304
#define TP       136                       // transpose-stage row pad (halfs)

__device__ __forceinline__ uint32_t sw_off(int row, int chunk) {
    return (uint32_t)(row * 128 + ((chunk ^ (row & 7)) << 4));
}

// ---------------------------------------------------------------------------
// One 128x128 GEMM tile, parameterized by (bm, bn, z).
// MODE 0: proj (K=768; z = weight slice; z<2 -> Q*alpha|K, z==2 -> V^T staged)
// MODE 1: exp(QK^T) (K=768;  z = batch; -> fp16 exp(logit), atomic row sums)
// MODE 2: P @ V^T   (K=2048; z = batch; -> fp32 d_out / row sum)
// ---------------------------------------------------------------------------
template <int MODE>
__device__ __forceinline__ void gemm_tile(
    char* smem,
    const __half* __restrict__ A, const __half* __restrict__ B,
    float* __restrict__ outF, __half* __restrict__ outH,
    __half* __restrict__ oQ, __half* __restrict__ oK,
    __half* __restrict__ oV,
    float* __restrict__ rsum,
    float alpha, int bm, int bn, int z)
{
    constexpr int  K  = (MODE == 2) ? 2048 : 768;
    constexpr long sA = (MODE == 0) ? 0L
                       : (MODE == 1) ? (long)SEQ * DIM : (long)SEQ * SEQ;
    constexpr long sB = (MODE == 0) ? (long)DIM * DIM
                       : (MODE == 1) ? (long)SEQ * DIM : (long)DIM * SEQ;
    constexpr int NC  = K / 64;

    const uint32_t sbase = smem_u32(smem);

    const int tid  = threadIdx.x;
    const int wid  = tid >> 5;
    const int lane = tid & 31;
    const int wm   = wid & 1;      // 0..1  (64-row half)
    const int wn   = wid >> 1;     // 0..1  (64-col half)

    const __half* gA = A + (long)z * sA + (long)bm * K;
    const __half* gB = B + (long)z * sB + (long)bn * K;

    auto load_stage = [&](int slot, int k0) {
        const uint32_t soff = sbase + slot * STAGE_B;
#pragma unroll
        for (int i = 0; i < 8; i++) {
            const int idx = tid + i * NTHREADS;
            const int row = idx >> 3, c = idx & 7;
            CP_ASYNC16(soff + sw_off(row, c), gA + (long)row * K + k0 + c * 8);
        }
#pragma unroll
        for (int i = 0; i < 8; i++) {
            const int idx = tid + i * NTHREADS;
            const int row = idx >> 3, c = idx & 7;
            CP_ASYNC16(soff + TILE_B + sw_off(row, c),
                       gB + (long)row * K + k0 + c * 8);
        }
        CP_COMMIT();
    };

    // ldmatrix per-thread addressing (precomputed per warp row)
    const int rA  = lane & 15;
    const int chA = lane >> 4;
    const int rB  = (lane & 7) | ((lane >> 4) << 3);
    const int chB = (lane >> 3) & 1;

    uint32_t aRow[4], aXor[4], bRow[4], bXor[4];
#pragma unroll
    for (int mf = 0; mf < 4; mf++) {
        const int row = wm * 64 + mf * 16 + rA;
        aRow[mf] = (uint32_t)(row * 128);
        aXor[mf] = (uint32_t)(row & 7);
    }
#pragma unroll
    for (int nf2 = 0; nf2 < 4; nf2++) {
        const int row = wn * 64 + nf2 * 16 + rB;
        bRow[nf2] = (uint32_t)(row * 128);
        bXor[nf2] = (uint32_t)(row & 7);
    }

    float acc[4][8][4];
#pragma unroll
    for (int mf = 0; mf < 4; mf++)
#pragma unroll
        for (int nf = 0; nf < 8; nf++)
#pragma unroll
            for (int q = 0; q < 4; q++) acc[mf][nf][q] = 0.0f;

    load_stage(0, 0);
    load_stage(1, 64);

    int slot = 0;
    for (int c = 0; c < NC; c++) {
        if (c + 1 < NC) { CP_WAIT1(); } else { CP_WAIT0(); }
        __syncthreads();
        if (c + 2 < NC) {
            const int ns = (slot + 2 >= NSTAGE) ? slot + 2 - NSTAGE : slot + 2;
            load_stage(ns, (c + 2) * 64);
        }

        const uint32_t aT = sbase + slot * STAGE_B;
        const uint32_t bT = aT + TILE_B;

#pragma unroll
        for (int ks = 0; ks < 4; ks++) {
            const uint32_t c2 = (uint32_t)(ks * 2);
            uint32_t ah[4][4], bh[8][2];
#pragma unroll
            for (int mf = 0; mf < 4; mf++)
                LDSM4(ah[mf], aT + aRow[mf] + (((c2 + chA) ^ aXor[mf]) << 4));
#pragma unroll
            for (int nf2 = 0; nf2 < 4; nf2++) {
                uint32_t th[4];
                LDSM4(th, bT + bRow[nf2] + (((c2 + chB) ^ bXor[nf2]) << 4));
                bh[nf2 * 2][0]     = th[0];
                bh[nf2 * 2][1]     = th[1];
                bh[nf2 * 2 + 1][0] = th[2];
                bh[nf2 * 2 + 1][1] = th[3];
            }
#pragma unroll
            for (int mf = 0; mf < 4; mf++)
#pragma unroll
                for (int nf = 0; nf < 8; nf++)
                    MMA_F16(acc[mf][nf], ah[mf], bh[nf]);
        }

        slot = (slot + 1 >= NSTAGE) ? 0 : slot + 1;
    }

    // -----------------------------------------------------------------------
    // Epilogue. Thread owns rows (gq, gq+8) per mf-frag, cols n0..n0+1 per nf.
    // -----------------------------------------------------------------------
    const int gq = lane >> 2;
    const int i2 = (lane & 3) * 2;

    if (MODE == 0 && z == 2) {
        // V slice: transpose through (now-dead) smem ring, coalesced V^T out.
        __syncthreads();  // all warps done reading the ring
        __half* tt = reinterpret_cast<__half*>(smem);
#pragma unroll
        for (int mf = 0; mf < 4; mf++)
#pragma unroll
            for (int h = 0; h < 2; h++) {
                const int ml = wm * 64 + mf * 16 + gq + h * 8;
#pragma unroll
                for (int nf = 0; nf < 8; nf++) {
                    const int nl = wn * 64 + nf * 8 + i2;
                    tt[(nl)     * TP + ml] = __float2half_rn(acc[mf][nf][h*2+0]);
                    tt[(nl + 1) * TP + ml] = __float2half_rn(acc[mf][nf][h*2+1]);
                }
            }
        __syncthreads();
        // Copy out: 128 d-rows x 128 s (256B contiguous per row).
        const int b  = bm >> 11;
        const int s0 = bm & 2047;
        const int cl = tid & 3;          // 4 lanes per row
#pragma unroll
        for (int i = 0; i < 4; i++) {
            const int r = i * 32 + (tid >> 2);
            __half* dst = oV + ((long)b * DIM + bn + r) * SEQ + s0;
#pragma unroll
            for (int u = 0; u < 4; u++) {
                const int ch = u * 4 + cl;   // 16 chunks of 8 halfs
                uint4 v = *reinterpret_cast<uint4*>(tt + r * TP + ch * 8);
                *reinterpret_cast<uint4*>(dst + ch * 8) = v;
            }
        }
        return;
    }

#pragma unroll
    for (int mf = 0; mf < 4; mf++) {
#pragma unroll
        for (int h = 0; h < 2; h++) {
            const int mg = bm + wm * 64 + mf * 16 + gq + h * 8;

            if (MODE == 1) {
                // exp (alpha pre-baked into Q) + unnormalized P + row sums
                float esum = 0.0f;
#pragma unroll
                for (int nf = 0; nf < 8; nf++) {
                    const int n0 = bn + wn * 64 + nf * 8 + i2;
                    const float e0 = __expf(acc[mf][nf][h * 2 + 0]);
                    const float e1 = __expf(acc[mf][nf][h * 2 + 1]);
                    esum += e0 + e1;
                    __half2 hv = __floats2half2_rn(e0, e1);
                    *reinterpret_cast<__half2*>(
                        outH + (long)z * SEQ * SEQ + (long)mg * SEQ + n0) = hv;
                }
                esum += __shfl_xor_sync(0xffffffff, esum, 1);
                esum += __shfl_xor_sync(0xffffffff, esum, 2);
                if ((lane & 3) == 0)
                    atomicAdd(&rsum[(long)z * SEQ + mg], esum);
            } else if (MODE == 2) {
                const float rs  = rsum[(long)z * SEQ + mg];
                const float inv = __fdividef(1.0f, rs);
#pragma unroll
                for (int nf = 0; nf < 8; nf++) {
                    const int n0 = bn + wn * 64 + nf * 8 + i2;
                    float* dst = outF + (long)z * SEQ * DIM + (long)mg * DIM + n0;
                    *reinterpret_cast<float2*>(dst) =
                        make_float2(acc[mf][nf][h * 2 + 0] * inv,
                                    acc[mf][nf][h * 2 + 1] * inv);
                }
            } else {  // MODE 0, z in {0,1}
#pragma unroll
                for (int nf = 0; nf < 8; nf++) {
                    const int n0 = bn + wn * 64 + nf * 8 + i2;
                    float f0 = acc[mf][nf][h * 2 + 0];
                    float f1 = acc[mf][nf][h * 2 + 1];
                    __half* dst;
                    if (z == 0) { dst = oQ; f0 *= alpha; f1 *= alpha; }
                    else        { dst = oK; }
                    __half2 hv = __floats2half2_rn(f0, f1);
                    *reinterpret_cast<__half2*>(dst + (long)mg * DIM + n0) = hv;
                }
            }
        }
    }
}

// ---------------------------------------------------------------------------
// Kernels
// ---------------------------------------------------------------------------

// QK projection only (z in {0,1})
__global__ void __launch_bounds__(NTHREADS, 2)
qk_proj_kernel(const __half* __restrict__ xh, const __half* __restrict__ wt,
               __half* __restrict__ oQ, __half* __restrict__ oK, float alpha)
{
    extern __shared__ char smem[];
    gemm_tile<0>(smem, xh, wt, nullptr, nullptr, oQ, oK, nullptr, nullptr,
                 alpha, blockIdx.y * 128, blockIdx.x * 128, blockIdx.z);
}

// Fused: V^T projection (768 blocks) + exp(QK^T) (2048 blocks).
// Heterogeneous CTAs co-resident on each SM fill each other's stalls.
#define NV_TILES 768
__global__ void __launch_bounds__(NTHREADS, 2)
attn_v_kernel(const __half* __restrict__ xh, const __half* __restrict__ wt,
              const __half* __restrict__ qh, const __half* __restrict__ kh,
              __half* __restrict__ oV, __half* __restrict__ ph,
              float* __restrict__ rsum)
{
    extern __shared__ char smem[];
    const int bid = blockIdx.x;
    if (bid < NV_TILES) {
        // V^T projection tile: bm over BS rows, bn over DIM
        gemm_tile<0>(smem, xh, wt, nullptr, nullptr, nullptr, nullptr, oV,
                     nullptr, 1.0f, (bid / 6) * 128, (bid % 6) * 128, 2);
    } else {
        const int u = bid - NV_TILES;
        gemm_tile<1>(smem, qh, kh, nullptr, ph, nullptr, nullptr, nullptr,
                     rsum, 1.0f,
                     ((u >> 4) & 15) * 128, (u & 15) * 128, u >> 8);
    }
}

// out = (P @ V^T) / rsum
__global__ void __launch_bounds__(NTHREADS, 2)
pv_kernel(const __half* __restrict__ ph, const __half* __restrict__ vth,
          float* __restrict__ out, float* __restrict__ rsum)
{
    extern __shared__ char smem[];
    gemm_tile<2>(smem, ph, vth, out, nullptr, nullptr, nullptr, nullptr,
                 rsum, 1.0f, blockIdx.y * 128, blockIdx.x * 128, blockIdx.z);
}

// ---------------------------------------------------------------------------
// Conversion kernels
// ---------------------------------------------------------------------------
__global__ void __launch_bounds__(256)
conv_x_kernel(const float* __restrict__ x, __half* __restrict__ xh,
              float* __restrict__ rsum)
{
    // Fold rsum zeroing into the first 16 blocks (16384 floats).
    if (blockIdx.x < 16) {
        float4 zz = make_float4(0.f, 0.f, 0.f, 0.f);
        *reinterpret_cast<float4*>(rsum + blockIdx.x * 1024 + threadIdx.x * 4) = zz;
    }
    const long i = ((long)blockIdx.x * 256 + threadIdx.x) * 4;
    float4 v = *reinterpret_cast<const float4*>(x + i);
    __half2 h01 = __floats2half2_rn(v.x, v.y);
    __half2 h23 = __floats2half2_rn(v.z, v.w);
    uint2 pack;
    pack.x = *reinterpret_cast<uint32_t*>(&h01);
    pack.y = *reinterpret_cast<uint32_t*>(&h23);
    *reinterpret_cast<uint2*>(xh + i) = pack;
}

// Transpose QKV weights: W[z][k][n] -> Wt[z][n][k] (fp16)
__global__ void __launch_bounds__(256)
conv_w_kernel(const float* __restrict__ W, __half* __restrict__ wt)
{
    __shared__ float tile[32][33];
    const int z  = blockIdx.z;
    const int bx = blockIdx.x * 32;   // n
    const int by = blockIdx.y * 32;   // k
    const int tx = threadIdx.x & 31;
    const int ty = threadIdx.x >> 5;  // 0..7
    const float* Wz = W + (long)z * DIM * DIM;
#pragma unroll
    for (int i = 0; i < 32; i += 8)
        tile[ty + i][tx] = Wz[(long)(by + ty + i) * DIM + (bx + tx)];
    __syncthreads();
    __half* tz = wt + (long)z * DIM * DIM;
#pragma unroll
    for (int i = 0; i < 32; i += 8)
        tz[(long)(bx + ty + i) * DIM + (by + tx)] =
            __float2half_rn(tile[tx][ty + i]);
}

// ---------------------------------------------------------------------------
// Launch
// ---------------------------------------------------------------------------
extern "C" void kernel_launch(void* const* d_in, const int* in_sizes, int n_in,
                              void* d_out, int out_size)
{
    const float* x   = (const float*)d_in[0];   // [B, S, D]
    const float* QKV = (const float*)d_in[1];   // [3, D, D]
    float* out = (float*)d_out;                 // [B, S, D]

    __half *xh, *wt, *qh, *kh, *vth, *ph;
    float* rsum;
    cudaGetSymbolAddress((void**)&xh,   g_xh);
    cudaGetSymbolAddress((void**)&wt,   g_wt);
    cudaGetSymbolAddress((void**)&qh,   g_qh);
    cudaGetSymbolAddress((void**)&kh,   g_kh);
    cudaGetSymbolAddress((void**)&vth,  g_vth);
    cudaGetSymbolAddress((void**)&ph,   g_ph);
    cudaGetSymbolAddress((void**)&rsum, g_rsum);

    cudaFuncSetAttribute(qk_proj_kernel, cudaFuncAttributeMaxDynamicSharedMemorySize, SMEM_TOTAL);
    cudaFuncSetAttribute(attn_v_kernel,  cudaFuncAttributeMaxDynamicSharedMemorySize, SMEM_TOTAL);
    cudaFuncSetAttribute(pv_kernel,      cudaFuncAttributeMaxDynamicSharedMemorySize, SMEM_TOTAL);

    const float scale = 1.0f / sqrtf((float)DIM);

    // 1) x -> fp16 (+ rsum zeroing folded in)
    conv_x_kernel<<<(BS * DIM) / 1024, 256>>>(x, xh, rsum);
    // 2) W -> W^T fp16
    conv_w_kernel<<<dim3(DIM / 32, DIM / 32, 3), 256>>>(QKV, wt);

    // 3) QK projection -> Q*scale | K
    qk_proj_kernel<<<dim3(DIM / 128, BS / 128, 2), NTHREADS, SMEM_TOTAL>>>(
        xh, wt, qh, kh, scale);

    // 4) fused: V^T projection + P = exp(Q@K^T) with atomic row sums
    attn_v_kernel<<<NV_TILES + SEQ / 128 * SEQ / 128 * BATCH, NTHREADS, SMEM_TOTAL>>>(
        xh, wt, qh, kh, vth, ph, rsum);

    // 5) out = (P @ V) / rsum
    pv_kernel<<<dim3(DIM / 128, SEQ / 128, BATCH), NTHREADS, SMEM_TOTAL>>>(
        ph, vth, out, rsum);
}

// round 17
// speedup vs baseline: 1.0087x; 1.0087x over previous
#include <cuda_runtime.h>
#include <cuda_fp16.h>
#include <math.h>
#include <stdint.h>

// ---------------------------------------------------------------------------
// Problem constants
// ---------------------------------------------------------------------------
#define BATCH 8
#define SEQ   2048
#define DIM   768
#define BS    (BATCH * SEQ)   // 16384

// ---------------------------------------------------------------------------
// Scratch (__device__ globals; no allocation allowed). All fp16 single-word.
// ---------------------------------------------------------------------------
__device__ __half g_xh [(size_t)BS * DIM];
__device__ __half g_wt [3ULL * DIM * DIM];            // W^T, [z][n][k]
__device__ __half g_qh [(size_t)BS * DIM];            // Q (pre-scaled by alpha)
__device__ __half g_kh [(size_t)BS * DIM];            // K
__device__ __half g_vth[(size_t)BATCH * DIM * SEQ];   // V^T: [b][d][s]
__device__ __half g_ph [(size_t)BATCH * SEQ * SEQ];   // un-normalized exp(S)
__device__ float  g_rsum[(size_t)BATCH * SEQ];        // per-row sum of exp

// ---------------------------------------------------------------------------
// Helpers
// ---------------------------------------------------------------------------
__device__ __forceinline__ uint32_t smem_u32(const void* p) {
    uint32_t a;
    asm("{ .reg .u64 t; cvta.to.shared.u64 t, %1; cvt.u32.u64 %0, t; }"
        : "=r"(a) : "l"(p));
    return a;
}

#define LDSM4(r, addr) \
    asm volatile("ldmatrix.sync.aligned.m8n8.x4.shared.b16 {%0,%1,%2,%3}, [%4];" \
        : "=r"((r)[0]), "=r"((r)[1]), "=r"((r)[2]), "=r"((r)[3]) : "r"(addr))

#define MMA_F16(d, a, b) \
    asm volatile("mma.sync.aligned.m16n8k16.row.col.f32.f16.f16.f32 " \
        "{%0,%1,%2,%3}, {%4,%5,%6,%7}, {%8,%9}, {%0,%1,%2,%3};" \
        : "+f"((d)[0]), "+f"((d)[1]), "+f"((d)[2]), "+f"((d)[3]) \
        : "r"((a)[0]), "r"((a)[1]), "r"((a)[2]), "r"((a)[3]), \
          "r"((b)[0]), "r"((b)[1]))

#define CP_ASYNC16(dst, src) \
    asm volatile("cp.async.cg.shared.global [%0], [%1], 16;" \
        :: "r"(dst), "l"(src))
#define CP_COMMIT()  asm volatile("cp.async.commit_group;")
#define CP_WAIT1()   asm volatile("cp.async.wait_group 1;")
#define CP_WAIT0()   asm volatile("cp.async.wait_group 0;")

// ---------------------------------------------------------------------------
// GEMM tiling: BM=128, BN=128, BK=64 fp16; 4 warps (2m x 2n), warp 64x64.
// Stage = A tile + B tile (16KB each) = 32KB, XOR-swizzled rows.
// 3-stage ring = 96KB/CTA; 128 threads, <=255 regs -> 2 CTAs/SM.
// ---------------------------------------------------------------------------
#define NTHREADS 128
#define TILE_B   16384
#define STAGE_B  (2 * TILE_B)              // 32768
#define NSTAGE   3
#define SMEM_TOTAL (NSTAGE * STAGE_B)      // 98304
#define TP       136                       // transpose-stage row pad (halfs)

__device__ __forceinline__ uint32_t sw_off(int row, int chunk) {
    return (uint32_t)(row * 128 + ((chunk ^ (row & 7)) << 4));
}

// ---------------------------------------------------------------------------
// One 128x128 GEMM tile, parameterized by (bm, bn, z).
// MODE 0: proj (K=768; z = weight slice; z<2 -> Q*alpha|K, z==2 -> V^T staged)
// MODE 1: exp(QK^T) (K=768;  z = batch; -> fp16 exp(logit), atomic row sums)
// MODE 2: P @ V^T   (K=2048; z = batch; -> fp32 d_out / row sum)
// ---------------------------------------------------------------------------
template <int MODE>
__device__ __forceinline__ void gemm_tile(
    char* smem,
    const __half* __restrict__ A, const __half* __restrict__ B,
    float* __restrict__ outF, __half* __restrict__ outH,
    __half* __restrict__ oQ, __half* __restrict__ oK,
    __half* __restrict__ oV,
    float* __restrict__ rsum,
    float alpha, int bm, int bn, int z)
{
    constexpr int  K  = (MODE == 2) ? 2048 : 768;
    constexpr long sA = (MODE == 0) ? 0L
                       : (MODE == 1) ? (long)SEQ * DIM : (long)SEQ * SEQ;
    constexpr long sB = (MODE == 0) ? (long)DIM * DIM
                       : (MODE == 1) ? (long)SEQ * DIM : (long)DIM * SEQ;
    constexpr int NC  = K / 64;

    const uint32_t sbase = smem_u32(smem);

    const int tid  = threadIdx.x;
    const int wid  = tid >> 5;
    const int lane = tid & 31;
    const int wm   = wid & 1;      // 0..1  (64-row half)
    const int wn   = wid >> 1;     // 0..1  (64-col half)

    const __half* gA = A + (long)z * sA + (long)bm * K;
    const __half* gB = B + (long)z * sB + (long)bn * K;

    auto load_stage = [&](int slot, int k0) {
        const uint32_t soff = sbase + slot * STAGE_B;
#pragma unroll
        for (int i = 0; i < 8; i++) {
            const int idx = tid + i * NTHREADS;
            const int row = idx >> 3, c = idx & 7;
            CP_ASYNC16(soff + sw_off(row, c), gA + (long)row * K + k0 + c * 8);
        }
#pragma unroll
        for (int i = 0; i < 8; i++) {
            const int idx = tid + i * NTHREADS;
            const int row = idx >> 3, c = idx & 7;
            CP_ASYNC16(soff + TILE_B + sw_off(row, c),
                       gB + (long)row * K + k0 + c * 8);
        }
        CP_COMMIT();
    };

    // ldmatrix per-thread addressing (precomputed per warp row)
    const int rA  = lane & 15;
    const int chA = lane >> 4;
    const int rB  = (lane & 7) | ((lane >> 4) << 3);
    const int chB = (lane >> 3) & 1;

    uint32_t aRow[4], aXor[4], bRow[4], bXor[4];
#pragma unroll
    for (int mf = 0; mf < 4; mf++) {
        const int row = wm * 64 + mf * 16 + rA;
        aRow[mf] = (uint32_t)(row * 128);
        aXor[mf] = (uint32_t)(row & 7);
    }
#pragma unroll
    for (int nf2 = 0; nf2 < 4; nf2++) {
        const int row = wn * 64 + nf2 * 16 + rB;
        bRow[nf2] = (uint32_t)(row * 128);
        bXor[nf2] = (uint32_t)(row & 7);
    }

    float acc[4][8][4];
#pragma unroll
    for (int mf = 0; mf < 4; mf++)
#pragma unroll
        for (int nf = 0; nf < 8; nf++)
#pragma unroll
            for (int q = 0; q < 4; q++) acc[mf][nf][q] = 0.0f;

    load_stage(0, 0);
    load_stage(1, 64);

    int slot = 0;
    for (int c = 0; c < NC; c++) {
        if (c + 1 < NC) { CP_WAIT1(); } else { CP_WAIT0(); }
        __syncthreads();
        if (c + 2 < NC) {
            const int ns = (slot + 2 >= NSTAGE) ? slot + 2 - NSTAGE : slot + 2;
            load_stage(ns, (c + 2) * 64);
        }

        const uint32_t aT = sbase + slot * STAGE_B;
        const uint32_t bT = aT + TILE_B;

#pragma unroll
        for (int ks = 0; ks < 4; ks++) {
            const uint32_t c2 = (uint32_t)(ks * 2);
            uint32_t ah[4][4], bh[8][2];
#pragma unroll
            for (int mf = 0; mf < 4; mf++)
                LDSM4(ah[mf], aT + aRow[mf] + (((c2 + chA) ^ aXor[mf]) << 4));
#pragma unroll
            for (int nf2 = 0; nf2 < 4; nf2++) {
                uint32_t th[4];
                LDSM4(th, bT + bRow[nf2] + (((c2 + chB) ^ bXor[nf2]) << 4));
                bh[nf2 * 2][0]     = th[0];
                bh[nf2 * 2][1]     = th[1];
                bh[nf2 * 2 + 1][0] = th[2];
                bh[nf2 * 2 + 1][1] = th[3];
            }
#pragma unroll
            for (int mf = 0; mf < 4; mf++)
#pragma unroll
                for (int nf = 0; nf < 8; nf++)
                    MMA_F16(acc[mf][nf], ah[mf], bh[nf]);
        }

        slot = (slot + 1 >= NSTAGE) ? 0 : slot + 1;
    }

    // -----------------------------------------------------------------------
    // Epilogue. Thread owns rows (gq, gq+8) per mf-frag, cols n0..n0+1 per nf.
    // -----------------------------------------------------------------------
    const int gq = lane >> 2;
    const int i2 = (lane & 3) * 2;

    if (MODE == 0 && z == 2) {
        // V slice: transpose through (now-dead) smem ring, coalesced V^T out.
        __syncthreads();  // all warps done reading the ring
        __half* tt = reinterpret_cast<__half*>(smem);
#pragma unroll
        for (int mf = 0; mf < 4; mf++)
#pragma unroll
            for (int h = 0; h < 2; h++) {
                const int ml = wm * 64 + mf * 16 + gq + h * 8;
#pragma unroll
                for (int nf = 0; nf < 8; nf++) {
                    const int nl = wn * 64 + nf * 8 + i2;
                    tt[(nl)     * TP + ml] = __float2half_rn(acc[mf][nf][h*2+0]);
                    tt[(nl + 1) * TP + ml] = __float2half_rn(acc[mf][nf][h*2+1]);
                }
            }
        __syncthreads();
        // Copy out: 128 d-rows x 128 s (256B contiguous per row).
        const int b  = bm >> 11;
        const int s0 = bm & 2047;
        const int cl = tid & 3;          // 4 lanes per row
#pragma unroll
        for (int i = 0; i < 4; i++) {
            const int r = i * 32 + (tid >> 2);
            __half* dst = oV + ((long)b * DIM + bn + r) * SEQ + s0;
#pragma unroll
            for (int u = 0; u < 4; u++) {
                const int ch = u * 4 + cl;   // 16 chunks of 8 halfs
                uint4 v = *reinterpret_cast<uint4*>(tt + r * TP + ch * 8);
                *reinterpret_cast<uint4*>(dst + ch * 8) = v;
            }
        }
        return;
    }

#pragma unroll
    for (int mf = 0; mf < 4; mf++) {
#pragma unroll
        for (int h = 0; h < 2; h++) {
            const int mg = bm + wm * 64 + mf * 16 + gq + h * 8;

            if (MODE == 1) {
                // exp (alpha pre-baked into Q) + unnormalized P + row sums
                float esum = 0.0f;
#pragma unroll
                for (int nf = 0; nf < 8; nf++) {
                    const int n0 = bn + wn * 64 + nf * 8 + i2;
                    const float e0 = __expf(acc[mf][nf][h * 2 + 0]);
                    const float e1 = __expf(acc[mf][nf][h * 2 + 1]);
                    esum += e0 + e1;
                    __half2 hv = __floats2half2_rn(e0, e1);
                    *reinterpret_cast<__half2*>(
                        outH + (long)z * SEQ * SEQ + (long)mg * SEQ + n0) = hv;
                }
                esum += __shfl_xor_sync(0xffffffff, esum, 1);
                esum += __shfl_xor_sync(0xffffffff, esum, 2);
                if ((lane & 3) == 0)
                    atomicAdd(&rsum[(long)z * SEQ + mg], esum);
            } else if (MODE == 2) {
                const float rs  = rsum[(long)z * SEQ + mg];
                const float inv = __fdividef(1.0f, rs);
#pragma unroll
                for (int nf = 0; nf < 8; nf++) {
                    const int n0 = bn + wn * 64 + nf * 8 + i2;
                    float* dst = outF + (long)z * SEQ * DIM + (long)mg * DIM + n0;
                    *reinterpret_cast<float2*>(dst) =
                        make_float2(acc[mf][nf][h * 2 + 0] * inv,
                                    acc[mf][nf][h * 2 + 1] * inv);
                }
            } else {  // MODE 0, z in {0,1}
#pragma unroll
                for (int nf = 0; nf < 8; nf++) {
                    const int n0 = bn + wn * 64 + nf * 8 + i2;
                    float f0 = acc[mf][nf][h * 2 + 0];
                    float f1 = acc[mf][nf][h * 2 + 1];
                    __half* dst;
                    if (z == 0) { dst = oQ; f0 *= alpha; f1 *= alpha; }
                    else        { dst = oK; }
                    __half2 hv = __floats2half2_rn(f0, f1);
                    *reinterpret_cast<__half2*>(dst + (long)mg * DIM + n0) = hv;
                }
            }
        }
    }
}

// ---------------------------------------------------------------------------
// Kernels
// ---------------------------------------------------------------------------

// QKV projection (z in {0,1,2}); grid (6, 128, 3) = 2304 CTAs
__global__ void __launch_bounds__(NTHREADS, 2)
proj_kernel(const __half* __restrict__ xh, const __half* __restrict__ wt,
            __half* __restrict__ oQ, __half* __restrict__ oK,
            __half* __restrict__ oV, float alpha)
{
    extern __shared__ char smem[];
    gemm_tile<0>(smem, xh, wt, nullptr, nullptr, oQ, oK, oV,
                 nullptr, alpha, blockIdx.y * 128, blockIdx.x * 128,
                 blockIdx.z);
}

// P = exp(Q @ K^T) (un-normalized) + atomic row sums; grid (16, 16, 8)
__global__ void __launch_bounds__(NTHREADS, 2)
attn_kernel(const __half* __restrict__ qh, const __half* __restrict__ kh,
            __half* __restrict__ ph, float* __restrict__ rsum)
{
    extern __shared__ char smem[];
    gemm_tile<1>(smem, qh, kh, nullptr, ph, nullptr, nullptr, nullptr,
                 rsum, 1.0f, blockIdx.y * 128, blockIdx.x * 128, blockIdx.z);
}

// out = (P @ V^T) / rsum; grid (6, 16, 8)
__global__ void __launch_bounds__(NTHREADS, 2)
pv_kernel(const __half* __restrict__ ph, const __half* __restrict__ vth,
          float* __restrict__ out, float* __restrict__ rsum)
{
    extern __shared__ char smem[];
    gemm_tile<2>(smem, ph, vth, out, nullptr, nullptr, nullptr, nullptr,
                 rsum, 1.0f, blockIdx.y * 128, blockIdx.x * 128, blockIdx.z);
}

// ---------------------------------------------------------------------------
// Fused conversion kernel: x->fp16 (12288 blocks), W->W^T fp16 (1728 blocks),
// rsum zeroing folded into the first 16 x-blocks. One launch total.
// ---------------------------------------------------------------------------
#define NXBLK 12288   // (BS*DIM)/1024
#define NWBLK 1728    // 24*24*3

__global__ void __launch_bounds__(256)
conv_fused_kernel(const float* __restrict__ x, __half* __restrict__ xh,
                  const float* __restrict__ W, __half* __restrict__ wt,
                  float* __restrict__ rsum)
{
    __shared__ float tile[32][33];
    const int bid = blockIdx.x;

    if (bid < NXBLK) {
        if (bid < 16) {
            float4 zz = make_float4(0.f, 0.f, 0.f, 0.f);
            *reinterpret_cast<float4*>(rsum + bid * 1024 + threadIdx.x * 4) = zz;
        }
        const long i = ((long)bid * 256 + threadIdx.x) * 4;
        float4 v = *reinterpret_cast<const float4*>(x + i);
        __half2 h01 = __floats2half2_rn(v.x, v.y);
        __half2 h23 = __floats2half2_rn(v.z, v.w);
        uint2 pack;
        pack.x = *reinterpret_cast<uint32_t*>(&h01);
        pack.y = *reinterpret_cast<uint32_t*>(&h23);
        *reinterpret_cast<uint2*>(xh + i) = pack;
        return;
    }

    // Weight transpose: W[z][k][n] -> Wt[z][n][k]
    const int u   = bid - NXBLK;
    const int z   = u / 576;           // 576 = 24*24
    const int rem = u - z * 576;
    const int by  = (rem / 24) * 32;   // k
    const int bx  = (rem % 24) * 32;   // n
    const int tx  = threadIdx.x & 31;
    const int ty  = threadIdx.x >> 5;  // 0..7
    const float* Wz = W + (long)z * DIM * DIM;
#pragma unroll
    for (int i = 0; i < 32; i += 8)
        tile[ty + i][tx] = Wz[(long)(by + ty + i) * DIM + (bx + tx)];
    __syncthreads();
    __half* tz = wt + (long)z * DIM * DIM;
#pragma unroll
    for (int i = 0; i < 32; i += 8)
        tz[(long)(bx + ty + i) * DIM + (by + tx)] =
            __float2half_rn(tile[tx][ty + i]);
}

// ---------------------------------------------------------------------------
// Launch
// ---------------------------------------------------------------------------
extern "C" void kernel_launch(void* const* d_in, const int* in_sizes, int n_in,
                              void* d_out, int out_size)
{
    const float* x   = (const float*)d_in[0];   // [B, S, D]
    const float* QKV = (const float*)d_in[1];   // [3, D, D]
    float* out = (float*)d_out;                 // [B, S, D]

    __half *xh, *wt, *qh, *kh, *vth, *ph;
    float* rsum;
    cudaGetSymbolAddress((void**)&xh,   g_xh);
    cudaGetSymbolAddress((void**)&wt,   g_wt);
    cudaGetSymbolAddress((void**)&qh,   g_qh);
    cudaGetSymbolAddress((void**)&kh,   g_kh);
    cudaGetSymbolAddress((void**)&vth,  g_vth);
    cudaGetSymbolAddress((void**)&ph,   g_ph);
    cudaGetSymbolAddress((void**)&rsum, g_rsum);

    cudaFuncSetAttribute(proj_kernel, cudaFuncAttributeMaxDynamicSharedMemorySize, SMEM_TOTAL);
    cudaFuncSetAttribute(attn_kernel, cudaFuncAttributeMaxDynamicSharedMemorySize, SMEM_TOTAL);
    cudaFuncSetAttribute(pv_kernel,   cudaFuncAttributeMaxDynamicSharedMemorySize, SMEM_TOTAL);

    const float scale = 1.0f / sqrtf((float)DIM);

    // 1) fused: x -> fp16, W -> W^T fp16, rsum zeroing (one launch)
    conv_fused_kernel<<<NXBLK + NWBLK, 256>>>(x, xh, QKV, wt, rsum);

    // 2) QKV projection -> Q*scale | K | V^T (staged transpose)
    proj_kernel<<<dim3(DIM / 128, BS / 128, 3), NTHREADS, SMEM_TOTAL>>>(
        xh, wt, qh, kh, vth, scale);

    // 3) P = exp(Q@K^T)  (un-normalized, scale pre-baked) + atomic row sums
    attn_kernel<<<dim3(SEQ / 128, SEQ / 128, BATCH), NTHREADS, SMEM_TOTAL>>>(
        qh, kh, ph, rsum);

    // 4) out = (P @ V) / rsum
    pv_kernel<<<dim3(DIM / 128, SEQ / 128, BATCH), NTHREADS, SMEM_TOTAL>>>(
        ph, vth, out, rsum);
}